// round 1
// baseline (speedup 1.0000x reference)
#include <cuda_runtime.h>
#include <math.h>

#define D_MODEL 1024
#define NHEADS  16
#define HD      64
#define SEQ     2048
#define BATCH   2
#define WIN     256

// Scratch (allocation-free: __device__ globals)
__device__ float g_Q[BATCH * NHEADS * SEQ * HD];   // [b][h][l][d]
__device__ float g_K[BATCH * NHEADS * SEQ * HD];
__device__ float g_V[BATCH * NHEADS * SEQ * HD];
__device__ float g_O[BATCH * SEQ * D_MODEL];       // [b][l][h*64+d]

// ---------------------------------------------------------------------------
// NT GEMM: C[m,n] = sum_k A[m,k] * W[n,k] + bias[n]
// MODE 0: route into g_Q/g_K/g_V head-major.  MODE 1: A = g_O, write Cout.
// 128x128 tile, BK=16, 256 threads, 8x8 microtile (split 4+4).
// ---------------------------------------------------------------------------
template <int MODE>
__global__ __launch_bounds__(256)
void gemm_nt(const float* __restrict__ A, const float* __restrict__ W,
             const float* __restrict__ bias, float* __restrict__ Cout,
             int M, int N, int K)
{
    __shared__ float As[16][128];
    __shared__ float Bs[16][128];

    const float* Ap = (MODE == 1) ? g_O : A;

    int tid = threadIdx.x;
    int bm = blockIdx.y * 128;
    int bn = blockIdx.x * 128;
    int ty = tid / 16;
    int tx = tid % 16;

    float acc[8][8];
#pragma unroll
    for (int i = 0; i < 8; i++)
#pragma unroll
        for (int j = 0; j < 8; j++) acc[i][j] = 0.f;

    for (int k0 = 0; k0 < K; k0 += 16) {
#pragma unroll
        for (int r = 0; r < 2; r++) {
            int linear = tid + r * 256;         // 0..511
            int row = linear >> 2;              // 0..127
            int v4  = linear & 3;               // float4 within 16
            float4 av = *(const float4*)(Ap + (size_t)(bm + row) * K + k0 + v4 * 4);
            As[v4 * 4 + 0][row] = av.x;
            As[v4 * 4 + 1][row] = av.y;
            As[v4 * 4 + 2][row] = av.z;
            As[v4 * 4 + 3][row] = av.w;
            float4 bv = *(const float4*)(W + (size_t)(bn + row) * K + k0 + v4 * 4);
            Bs[v4 * 4 + 0][row] = bv.x;
            Bs[v4 * 4 + 1][row] = bv.y;
            Bs[v4 * 4 + 2][row] = bv.z;
            Bs[v4 * 4 + 3][row] = bv.w;
        }
        __syncthreads();

#pragma unroll
        for (int kk = 0; kk < 16; kk++) {
            float4 a0 = *(const float4*)&As[kk][ty * 4];
            float4 a1 = *(const float4*)&As[kk][ty * 4 + 64];
            float4 b0 = *(const float4*)&Bs[kk][tx * 4];
            float4 b1 = *(const float4*)&Bs[kk][tx * 4 + 64];
            float a[8] = {a0.x, a0.y, a0.z, a0.w, a1.x, a1.y, a1.z, a1.w};
            float b[8] = {b0.x, b0.y, b0.z, b0.w, b1.x, b1.y, b1.z, b1.w};
#pragma unroll
            for (int i = 0; i < 8; i++)
#pragma unroll
                for (int j = 0; j < 8; j++) acc[i][j] += a[i] * b[j];
        }
        __syncthreads();
    }

#pragma unroll
    for (int i = 0; i < 8; i++) {
        int m = bm + ((i < 4) ? (ty * 4 + i) : (64 + ty * 4 + i - 4));
#pragma unroll
        for (int j = 0; j < 8; j++) {
            int n = bn + ((j < 4) ? (tx * 4 + j) : (64 + tx * 4 + j - 4));
            float v = acc[i][j] + bias[n];
            if (MODE == 0) {
                int part   = n >> 10;
                int within = n & 1023;
                int h = within >> 6;
                int d = within & 63;
                int b = m >> 11;   // /2048
                int l = m & 2047;
                size_t dst = ((size_t)(b * NHEADS + h) * SEQ + l) * HD + d;
                float* base = (part == 0) ? g_Q : (part == 1) ? g_K : g_V;
                base[dst] = v;
            } else {
                Cout[(size_t)m * N + n] = v;
            }
        }
    }
}

// ---------------------------------------------------------------------------
// Sliding-window attention. One CTA = (b*h, 64-query tile). 256 threads.
// Smem: Qs[d][q] (transposed), Ks[d][j] (transposed), Vs[j][d], Ps[j][68].
// ---------------------------------------------------------------------------
__global__ __launch_bounds__(256)
void attn_kernel()
{
    extern __shared__ float sm[];
    float* Qs = sm;                 // 64*64, Qs[d*64+q]
    float* Ks = sm + 64 * 64;       // 64*64, Ks[d*64+j]
    float* Vs = sm + 2 * 64 * 64;   // 64*64, Vs[j*64+d]
    float* Ps = sm + 3 * 64 * 64;   // 64*68, Ps[j*68+q]

    int tid = threadIdx.x;
    int bh  = blockIdx.y;           // 0..B*H-1
    int i0  = blockIdx.x * 64;

    const float* Qg = g_Q + (size_t)bh * SEQ * HD;
    const float* Kg = g_K + (size_t)bh * SEQ * HD;
    const float* Vg = g_V + (size_t)bh * SEQ * HD;

    int ty = tid / 16;
    int tx = tid % 16;

    // Load Q tile transposed (scaled by 1/sqrt(64) = 0.125)
#pragma unroll
    for (int r = 0; r < 4; r++) {
        int q  = tid >> 2;                 // 0..63
        int v4 = (tid & 3) + r * 4;        // 0..15 (float4 idx within row)
        float4 qv = *(const float4*)(Qg + (size_t)(i0 + q) * HD + v4 * 4);
        Qs[(v4 * 4 + 0) * 64 + q] = qv.x * 0.125f;
        Qs[(v4 * 4 + 1) * 64 + q] = qv.y * 0.125f;
        Qs[(v4 * 4 + 2) * 64 + q] = qv.z * 0.125f;
        Qs[(v4 * 4 + 3) * 64 + q] = qv.w * 0.125f;
    }
    __syncthreads();

    float m_r[4], l_r[4], o[4][4];
#pragma unroll
    for (int r = 0; r < 4; r++) {
        m_r[r] = -1e30f;
        l_r[r] = 0.f;
#pragma unroll
        for (int c = 0; c < 4; c++) o[r][c] = 0.f;
    }

    int kv_lo = i0 - (WIN - 1);
    if (kv_lo < 0) kv_lo = 0;
    int cs0 = (kv_lo / 64) * 64;

    for (int cs = cs0; cs < i0 + 64; cs += 64) {
        // Load K chunk (transposed) and V chunk (natural)
#pragma unroll
        for (int r = 0; r < 4; r++) {
            int j  = tid >> 2;
            int v4 = (tid & 3) + r * 4;
            float4 kv = *(const float4*)(Kg + (size_t)(cs + j) * HD + v4 * 4);
            Ks[(v4 * 4 + 0) * 64 + j] = kv.x;
            Ks[(v4 * 4 + 1) * 64 + j] = kv.y;
            Ks[(v4 * 4 + 2) * 64 + j] = kv.z;
            Ks[(v4 * 4 + 3) * 64 + j] = kv.w;
            float4 vv = *(const float4*)(Vg + (size_t)(cs + j) * HD + v4 * 4);
            *(float4*)&Vs[j * 64 + v4 * 4] = vv;
        }
        __syncthreads();

        // S = (Q*scale) @ K^T  — each thread 4x4
        float s[4][4];
#pragma unroll
        for (int r = 0; r < 4; r++)
#pragma unroll
            for (int c = 0; c < 4; c++) s[r][c] = 0.f;

#pragma unroll
        for (int d = 0; d < 64; d++) {
            float4 a = *(const float4*)&Qs[d * 64 + ty * 4];
            float4 b = *(const float4*)&Ks[d * 64 + tx * 4];
            float av[4] = {a.x, a.y, a.z, a.w};
            float bv[4] = {b.x, b.y, b.z, b.w};
#pragma unroll
            for (int r = 0; r < 4; r++)
#pragma unroll
                for (int c = 0; c < 4; c++) s[r][c] += av[r] * bv[c];
        }

        // mask + online softmax (row reductions across 16 lanes = half warp)
#pragma unroll
        for (int r = 0; r < 4; r++) {
            int iq = i0 + ty * 4 + r;
            bool allow[4];
            float rowmax = -1e30f;
#pragma unroll
            for (int c = 0; c < 4; c++) {
                int j = cs + tx * 4 + c;
                allow[c] = (j <= iq) && (j > iq - WIN);
                if (!allow[c]) s[r][c] = -1e30f;
                rowmax = fmaxf(rowmax, s[r][c]);
            }
#pragma unroll
            for (int msk = 1; msk < 16; msk <<= 1)
                rowmax = fmaxf(rowmax, __shfl_xor_sync(0xffffffffu, rowmax, msk));

            float mnew = fmaxf(m_r[r], rowmax);
            float corr = __expf(m_r[r] - mnew);
            m_r[r] = mnew;

            float rs = 0.f;
#pragma unroll
            for (int c = 0; c < 4; c++) {
                float p = allow[c] ? __expf(s[r][c] - mnew) : 0.f;
                s[r][c] = p;
                rs += p;
            }
#pragma unroll
            for (int msk = 1; msk < 16; msk <<= 1)
                rs += __shfl_xor_sync(0xffffffffu, rs, msk);

            l_r[r] = l_r[r] * corr + rs;
#pragma unroll
            for (int c = 0; c < 4; c++) o[r][c] *= corr;

            // write P transposed: Ps[j][q]
#pragma unroll
            for (int c = 0; c < 4; c++)
                Ps[(tx * 4 + c) * 68 + ty * 4 + r] = s[r][c];
        }
        __syncthreads();

        // O += P @ V  — thread owns rows q=ty*4+r, dims d=tx*4+c
#pragma unroll
        for (int j = 0; j < 64; j++) {
            float4 vb = *(const float4*)&Vs[j * 64 + tx * 4];
            float vv[4] = {vb.x, vb.y, vb.z, vb.w};
            float pa[4];
#pragma unroll
            for (int r = 0; r < 4; r++) pa[r] = Ps[j * 68 + ty * 4 + r];
#pragma unroll
            for (int r = 0; r < 4; r++)
#pragma unroll
                for (int c = 0; c < 4; c++) o[r][c] += pa[r] * vv[c];
        }
        __syncthreads();
    }

    // write normalized output: g_O[(b*SEQ + i)*1024 + h*64 + d]
    int b = bh / NHEADS;
    int h = bh % NHEADS;
#pragma unroll
    for (int r = 0; r < 4; r++) {
        int iq = i0 + ty * 4 + r;
        float inv = 1.f / l_r[r];
        float4 ov;
        ov.x = o[r][0] * inv;
        ov.y = o[r][1] * inv;
        ov.z = o[r][2] * inv;
        ov.w = o[r][3] * inv;
        *(float4*)(g_O + ((size_t)(b * SEQ + iq)) * D_MODEL + h * HD + tx * 4) = ov;
    }
}

// ---------------------------------------------------------------------------
extern "C" void kernel_launch(void* const* d_in, const int* in_sizes, int n_in,
                              void* d_out, int out_size)
{
    const float* x  = (const float*)d_in[0];   // [2,2048,1024]
    const float* w1 = (const float*)d_in[1];   // [3072,1024]
    const float* b1 = (const float*)d_in[2];   // [3072]
    const float* w2 = (const float*)d_in[3];   // [1024,1024]
    const float* b2 = (const float*)d_in[4];   // [1024]
    float* out = (float*)d_out;                // [2,2048,1024]

    const int M = BATCH * SEQ;                 // 4096

    // 1) QKV projection, routed into g_Q/g_K/g_V
    {
        dim3 grid(3 * D_MODEL / 128, M / 128); // 24 x 32
        gemm_nt<0><<<grid, 256>>>(x, w1, b1, nullptr, M, 3 * D_MODEL, D_MODEL);
    }

    // 2) Sliding-window attention
    {
        int smem = (3 * 64 * 64 + 64 * 68) * sizeof(float);  // 66560 B
        cudaFuncSetAttribute(attn_kernel,
                             cudaFuncAttributeMaxDynamicSharedMemorySize, smem);
        dim3 grid(SEQ / 64, BATCH * NHEADS);   // 32 x 32
        attn_kernel<<<grid, 256, smem>>>();
    }

    // 3) Output projection
    {
        dim3 grid(D_MODEL / 128, M / 128);     // 8 x 32
        gemm_nt<1><<<grid, 256>>>(nullptr, w2, b2, out, M, D_MODEL, D_MODEL);
    }
}

// round 2
// speedup vs baseline: 2.2290x; 2.2290x over previous
#include <cuda_runtime.h>
#include <math.h>

#define D_MODEL 1024
#define NHEADS  16
#define HD      64
#define SEQ     2048
#define BATCH   2
#define WIN     256

// Scratch (allocation-free: __device__ globals)
__device__ float g_Q[BATCH * NHEADS * SEQ * HD];   // [b][h][l][d]
__device__ float g_K[BATCH * NHEADS * SEQ * HD];
__device__ float g_V[BATCH * NHEADS * SEQ * HD];
__device__ float g_O[BATCH * SEQ * D_MODEL];       // [b][l][h*64+d]

__device__ __forceinline__ unsigned f2tf32(float f) {
    unsigned r;
    asm("cvt.rna.tf32.f32 %0, %1;" : "=r"(r) : "f"(f));
    return r;
}

__device__ __forceinline__ void mma_tf32(float c[4], const unsigned a[4], const unsigned b[2]) {
    asm volatile(
        "mma.sync.aligned.m16n8k8.row.col.f32.tf32.tf32.f32 "
        "{%0,%1,%2,%3}, {%4,%5,%6,%7}, {%8,%9}, {%0,%1,%2,%3};\n"
        : "+f"(c[0]), "+f"(c[1]), "+f"(c[2]), "+f"(c[3])
        : "r"(a[0]), "r"(a[1]), "r"(a[2]), "r"(a[3]),
          "r"(b[0]), "r"(b[1]));
}

// ---------------------------------------------------------------------------
// TF32 NT GEMM: C[m,n] = sum_k A[m,k] * W[n,k] + bias[n]
// MODE 0: route into g_Q/g_K/g_V head-major.  MODE 1: A = g_O, write Cout.
// BM=BN=128, BK=32, 256 threads (8 warps as 2x4), warp tile 64x32 (4x4 mmas).
// Smem stride 36 words => fragment loads are bank-conflict-free (bank=4r+c).
// ---------------------------------------------------------------------------
#define SSTR 36

template <int MODE>
__global__ __launch_bounds__(256)
void gemm_tf32(const float* __restrict__ A, const float* __restrict__ W,
               const float* __restrict__ bias, float* __restrict__ Cout,
               int M, int N, int K)
{
    __shared__ unsigned As[128 * SSTR];
    __shared__ unsigned Bs[128 * SSTR];

    const float* Ap = (MODE == 1) ? g_O : A;

    int tid  = threadIdx.x;
    int lane = tid & 31;
    int wid  = tid >> 5;
    int wm = (wid >> 2) * 64;      // 0 or 64
    int wn = (wid & 3) * 32;       // 0,32,64,96
    int bm = blockIdx.y * 128;
    int bn = blockIdx.x * 128;

    int g = lane >> 2;             // groupID 0..7
    int t = lane & 3;              // threadID_in_group 0..3

    float acc[4][4][4];
#pragma unroll
    for (int mt = 0; mt < 4; mt++)
#pragma unroll
        for (int nt = 0; nt < 4; nt++)
#pragma unroll
            for (int i = 0; i < 4; i++) acc[mt][nt][i] = 0.f;

    for (int k0 = 0; k0 < K; k0 += 32) {
        // Stage A and W tiles (convert fp32 -> tf32 on the way in)
#pragma unroll
        for (int r = 0; r < 4; r++) {
            int row = (tid >> 3) + r * 32;          // 0..127
            int c4  = (tid & 7) * 4;                // 0..28
            float4 av = *(const float4*)(Ap + (size_t)(bm + row) * K + k0 + c4);
            unsigned* da = &As[row * SSTR + c4];
            da[0] = f2tf32(av.x); da[1] = f2tf32(av.y);
            da[2] = f2tf32(av.z); da[3] = f2tf32(av.w);
            float4 bv = *(const float4*)(W + (size_t)(bn + row) * K + k0 + c4);
            unsigned* db = &Bs[row * SSTR + c4];
            db[0] = f2tf32(bv.x); db[1] = f2tf32(bv.y);
            db[2] = f2tf32(bv.z); db[3] = f2tf32(bv.w);
        }
        __syncthreads();

#pragma unroll
        for (int ks = 0; ks < 4; ks++) {
            int kk = ks * 8;
            unsigned af[4][4], bf[4][2];
#pragma unroll
            for (int mt = 0; mt < 4; mt++) {
                int r = wm + mt * 16 + g;
                int c = kk + t;
                af[mt][0] = As[r * SSTR + c];
                af[mt][1] = As[(r + 8) * SSTR + c];
                af[mt][2] = As[r * SSTR + c + 4];
                af[mt][3] = As[(r + 8) * SSTR + c + 4];
            }
#pragma unroll
            for (int nt = 0; nt < 4; nt++) {
                int n = wn + nt * 8 + g;
                int c = kk + t;
                bf[nt][0] = Bs[n * SSTR + c];
                bf[nt][1] = Bs[n * SSTR + c + 4];
            }
#pragma unroll
            for (int mt = 0; mt < 4; mt++)
#pragma unroll
                for (int nt = 0; nt < 4; nt++)
                    mma_tf32(acc[mt][nt], af[mt], bf[nt]);
        }
        __syncthreads();
    }

    // Epilogue: c0->(m,n) c1->(m,n+1) c2->(m+8,n) c3->(m+8,n+1)
#pragma unroll
    for (int mt = 0; mt < 4; mt++) {
#pragma unroll
        for (int nt = 0; nt < 4; nt++) {
#pragma unroll
            for (int i = 0; i < 4; i++) {
                int m = bm + wm + mt * 16 + g + ((i >> 1) ? 8 : 0);
                int n = bn + wn + nt * 8 + t * 2 + (i & 1);
                float v = acc[mt][nt][i] + bias[n];
                if (MODE == 0) {
                    int part   = n >> 10;
                    int within = n & 1023;
                    int h = within >> 6;
                    int d = within & 63;
                    int b = m >> 11;
                    int l = m & 2047;
                    size_t dst = ((size_t)(b * NHEADS + h) * SEQ + l) * HD + d;
                    float* base = (part == 0) ? g_Q : (part == 1) ? g_K : g_V;
                    base[dst] = v;
                } else {
                    Cout[(size_t)m * N + n] = v;
                }
            }
        }
    }
}

// ---------------------------------------------------------------------------
// Sliding-window attention (unchanged from R1). One CTA = (b*h, 64-query tile).
// ---------------------------------------------------------------------------
__global__ __launch_bounds__(256)
void attn_kernel()
{
    extern __shared__ float sm[];
    float* Qs = sm;                 // 64*64, Qs[d*64+q]
    float* Ks = sm + 64 * 64;       // 64*64, Ks[d*64+j]
    float* Vs = sm + 2 * 64 * 64;   // 64*64, Vs[j*64+d]
    float* Ps = sm + 3 * 64 * 64;   // 64*68, Ps[j*68+q]

    int tid = threadIdx.x;
    int bh  = blockIdx.y;
    int i0  = blockIdx.x * 64;

    const float* Qg = g_Q + (size_t)bh * SEQ * HD;
    const float* Kg = g_K + (size_t)bh * SEQ * HD;
    const float* Vg = g_V + (size_t)bh * SEQ * HD;

    int ty = tid / 16;
    int tx = tid % 16;

#pragma unroll
    for (int r = 0; r < 4; r++) {
        int q  = tid >> 2;
        int v4 = (tid & 3) + r * 4;
        float4 qv = *(const float4*)(Qg + (size_t)(i0 + q) * HD + v4 * 4);
        Qs[(v4 * 4 + 0) * 64 + q] = qv.x * 0.125f;
        Qs[(v4 * 4 + 1) * 64 + q] = qv.y * 0.125f;
        Qs[(v4 * 4 + 2) * 64 + q] = qv.z * 0.125f;
        Qs[(v4 * 4 + 3) * 64 + q] = qv.w * 0.125f;
    }
    __syncthreads();

    float m_r[4], l_r[4], o[4][4];
#pragma unroll
    for (int r = 0; r < 4; r++) {
        m_r[r] = -1e30f;
        l_r[r] = 0.f;
#pragma unroll
        for (int c = 0; c < 4; c++) o[r][c] = 0.f;
    }

    int kv_lo = i0 - (WIN - 1);
    if (kv_lo < 0) kv_lo = 0;
    int cs0 = (kv_lo / 64) * 64;

    for (int cs = cs0; cs < i0 + 64; cs += 64) {
#pragma unroll
        for (int r = 0; r < 4; r++) {
            int j  = tid >> 2;
            int v4 = (tid & 3) + r * 4;
            float4 kv = *(const float4*)(Kg + (size_t)(cs + j) * HD + v4 * 4);
            Ks[(v4 * 4 + 0) * 64 + j] = kv.x;
            Ks[(v4 * 4 + 1) * 64 + j] = kv.y;
            Ks[(v4 * 4 + 2) * 64 + j] = kv.z;
            Ks[(v4 * 4 + 3) * 64 + j] = kv.w;
            float4 vv = *(const float4*)(Vg + (size_t)(cs + j) * HD + v4 * 4);
            *(float4*)&Vs[j * 64 + v4 * 4] = vv;
        }
        __syncthreads();

        float s[4][4];
#pragma unroll
        for (int r = 0; r < 4; r++)
#pragma unroll
            for (int c = 0; c < 4; c++) s[r][c] = 0.f;

#pragma unroll
        for (int d = 0; d < 64; d++) {
            float4 a = *(const float4*)&Qs[d * 64 + ty * 4];
            float4 b = *(const float4*)&Ks[d * 64 + tx * 4];
            float av[4] = {a.x, a.y, a.z, a.w};
            float bv[4] = {b.x, b.y, b.z, b.w};
#pragma unroll
            for (int r = 0; r < 4; r++)
#pragma unroll
                for (int c = 0; c < 4; c++) s[r][c] += av[r] * bv[c];
        }

#pragma unroll
        for (int r = 0; r < 4; r++) {
            int iq = i0 + ty * 4 + r;
            bool allow[4];
            float rowmax = -1e30f;
#pragma unroll
            for (int c = 0; c < 4; c++) {
                int j = cs + tx * 4 + c;
                allow[c] = (j <= iq) && (j > iq - WIN);
                if (!allow[c]) s[r][c] = -1e30f;
                rowmax = fmaxf(rowmax, s[r][c]);
            }
#pragma unroll
            for (int msk = 1; msk < 16; msk <<= 1)
                rowmax = fmaxf(rowmax, __shfl_xor_sync(0xffffffffu, rowmax, msk));

            float mnew = fmaxf(m_r[r], rowmax);
            float corr = __expf(m_r[r] - mnew);
            m_r[r] = mnew;

            float rs = 0.f;
#pragma unroll
            for (int c = 0; c < 4; c++) {
                float p = allow[c] ? __expf(s[r][c] - mnew) : 0.f;
                s[r][c] = p;
                rs += p;
            }
#pragma unroll
            for (int msk = 1; msk < 16; msk <<= 1)
                rs += __shfl_xor_sync(0xffffffffu, rs, msk);

            l_r[r] = l_r[r] * corr + rs;
#pragma unroll
            for (int c = 0; c < 4; c++) o[r][c] *= corr;

#pragma unroll
            for (int c = 0; c < 4; c++)
                Ps[(tx * 4 + c) * 68 + ty * 4 + r] = s[r][c];
        }
        __syncthreads();

#pragma unroll
        for (int j = 0; j < 64; j++) {
            float4 vb = *(const float4*)&Vs[j * 64 + tx * 4];
            float vv[4] = {vb.x, vb.y, vb.z, vb.w};
            float pa[4];
#pragma unroll
            for (int r = 0; r < 4; r++) pa[r] = Ps[j * 68 + ty * 4 + r];
#pragma unroll
            for (int r = 0; r < 4; r++)
#pragma unroll
                for (int c = 0; c < 4; c++) o[r][c] += pa[r] * vv[c];
        }
        __syncthreads();
    }

    int b = bh / NHEADS;
    int h = bh % NHEADS;
#pragma unroll
    for (int r = 0; r < 4; r++) {
        int iq = i0 + ty * 4 + r;
        float inv = 1.f / l_r[r];
        float4 ov;
        ov.x = o[r][0] * inv;
        ov.y = o[r][1] * inv;
        ov.z = o[r][2] * inv;
        ov.w = o[r][3] * inv;
        *(float4*)(g_O + ((size_t)(b * SEQ + iq)) * D_MODEL + h * HD + tx * 4) = ov;
    }
}

// ---------------------------------------------------------------------------
extern "C" void kernel_launch(void* const* d_in, const int* in_sizes, int n_in,
                              void* d_out, int out_size)
{
    const float* x  = (const float*)d_in[0];   // [2,2048,1024]
    const float* w1 = (const float*)d_in[1];   // [3072,1024]
    const float* b1 = (const float*)d_in[2];   // [3072]
    const float* w2 = (const float*)d_in[3];   // [1024,1024]
    const float* b2 = (const float*)d_in[4];   // [1024]
    float* out = (float*)d_out;                // [2,2048,1024]

    const int M = BATCH * SEQ;                 // 4096

    // 1) QKV projection (tf32 tensor cores), routed into g_Q/g_K/g_V
    {
        dim3 grid(3 * D_MODEL / 128, M / 128); // 24 x 32
        gemm_tf32<0><<<grid, 256>>>(x, w1, b1, nullptr, M, 3 * D_MODEL, D_MODEL);
    }

    // 2) Sliding-window attention
    {
        int smem = (3 * 64 * 64 + 64 * 68) * sizeof(float);  // 66560 B
        cudaFuncSetAttribute(attn_kernel,
                             cudaFuncAttributeMaxDynamicSharedMemorySize, smem);
        dim3 grid(SEQ / 64, BATCH * NHEADS);   // 32 x 32
        attn_kernel<<<grid, 256, smem>>>();
    }

    // 3) Output projection (tf32 tensor cores)
    {
        dim3 grid(D_MODEL / 128, M / 128);     // 8 x 32
        gemm_tf32<1><<<grid, 256>>>(nullptr, w2, b2, out, M, D_MODEL, D_MODEL);
    }
}

// round 3
// speedup vs baseline: 2.6973x; 1.2101x over previous
#include <cuda_runtime.h>
#include <math.h>

#define D_MODEL 1024
#define NHEADS  16
#define HD      64
#define SEQ     2048
#define BATCH   2
#define WIN     256

// Scratch (allocation-free: __device__ globals)
__device__ float g_Q[BATCH * NHEADS * SEQ * HD];   // [b][h][l][d]
__device__ float g_K[BATCH * NHEADS * SEQ * HD];
__device__ float g_V[BATCH * NHEADS * SEQ * HD];
__device__ float g_O[BATCH * SEQ * D_MODEL];       // [b][l][h*64+d]

__device__ __forceinline__ unsigned f2tf32(float f) {
    unsigned r;
    asm("cvt.rna.tf32.f32 %0, %1;" : "=r"(r) : "f"(f));
    return r;
}

__device__ __forceinline__ void mma_tf32(float c[4], const unsigned a[4], const unsigned b[2]) {
    asm volatile(
        "mma.sync.aligned.m16n8k8.row.col.f32.tf32.tf32.f32 "
        "{%0,%1,%2,%3}, {%4,%5,%6,%7}, {%8,%9}, {%0,%1,%2,%3};\n"
        : "+f"(c[0]), "+f"(c[1]), "+f"(c[2]), "+f"(c[3])
        : "r"(a[0]), "r"(a[1]), "r"(a[2]), "r"(a[3]),
          "r"(b[0]), "r"(b[1]));
}

// ---------------------------------------------------------------------------
// TF32 NT GEMM: C[m,n] = sum_k A[m,k] * W[n,k] + bias[n]   (unchanged from R2)
// ---------------------------------------------------------------------------
#define SSTR 36

template <int MODE>
__global__ __launch_bounds__(256)
void gemm_tf32(const float* __restrict__ A, const float* __restrict__ W,
               const float* __restrict__ bias, float* __restrict__ Cout,
               int M, int N, int K)
{
    __shared__ unsigned As[128 * SSTR];
    __shared__ unsigned Bs[128 * SSTR];

    const float* Ap = (MODE == 1) ? g_O : A;

    int tid  = threadIdx.x;
    int lane = tid & 31;
    int wid  = tid >> 5;
    int wm = (wid >> 2) * 64;
    int wn = (wid & 3) * 32;
    int bm = blockIdx.y * 128;
    int bn = blockIdx.x * 128;

    int g = lane >> 2;
    int t = lane & 3;

    float acc[4][4][4];
#pragma unroll
    for (int mt = 0; mt < 4; mt++)
#pragma unroll
        for (int nt = 0; nt < 4; nt++)
#pragma unroll
            for (int i = 0; i < 4; i++) acc[mt][nt][i] = 0.f;

    for (int k0 = 0; k0 < K; k0 += 32) {
#pragma unroll
        for (int r = 0; r < 4; r++) {
            int row = (tid >> 3) + r * 32;
            int c4  = (tid & 7) * 4;
            float4 av = *(const float4*)(Ap + (size_t)(bm + row) * K + k0 + c4);
            unsigned* da = &As[row * SSTR + c4];
            da[0] = f2tf32(av.x); da[1] = f2tf32(av.y);
            da[2] = f2tf32(av.z); da[3] = f2tf32(av.w);
            float4 bv = *(const float4*)(W + (size_t)(bn + row) * K + k0 + c4);
            unsigned* db = &Bs[row * SSTR + c4];
            db[0] = f2tf32(bv.x); db[1] = f2tf32(bv.y);
            db[2] = f2tf32(bv.z); db[3] = f2tf32(bv.w);
        }
        __syncthreads();

#pragma unroll
        for (int ks = 0; ks < 4; ks++) {
            int kk = ks * 8;
            unsigned af[4][4], bf[4][2];
#pragma unroll
            for (int mt = 0; mt < 4; mt++) {
                int r = wm + mt * 16 + g;
                int c = kk + t;
                af[mt][0] = As[r * SSTR + c];
                af[mt][1] = As[(r + 8) * SSTR + c];
                af[mt][2] = As[r * SSTR + c + 4];
                af[mt][3] = As[(r + 8) * SSTR + c + 4];
            }
#pragma unroll
            for (int nt = 0; nt < 4; nt++) {
                int n = wn + nt * 8 + g;
                int c = kk + t;
                bf[nt][0] = Bs[n * SSTR + c];
                bf[nt][1] = Bs[n * SSTR + c + 4];
            }
#pragma unroll
            for (int mt = 0; mt < 4; mt++)
#pragma unroll
                for (int nt = 0; nt < 4; nt++)
                    mma_tf32(acc[mt][nt], af[mt], bf[nt]);
        }
        __syncthreads();
    }

#pragma unroll
    for (int mt = 0; mt < 4; mt++) {
#pragma unroll
        for (int nt = 0; nt < 4; nt++) {
#pragma unroll
            for (int i = 0; i < 4; i++) {
                int m = bm + wm + mt * 16 + g + ((i >> 1) ? 8 : 0);
                int n = bn + wn + nt * 8 + t * 2 + (i & 1);
                float v = acc[mt][nt][i] + bias[n];
                if (MODE == 0) {
                    int part   = n >> 10;
                    int within = n & 1023;
                    int h = within >> 6;
                    int d = within & 63;
                    int b = m >> 11;
                    int l = m & 2047;
                    size_t dst = ((size_t)(b * NHEADS + h) * SEQ + l) * HD + d;
                    float* base = (part == 0) ? g_Q : (part == 1) ? g_K : g_V;
                    base[dst] = v;
                } else {
                    Cout[(size_t)m * N + n] = v;
                }
            }
        }
    }
}

// ---------------------------------------------------------------------------
// Sliding-window attention with tf32 tensor cores.
// One CTA = (b*h, 64-query tile), 128 threads (4 warps, warp = 16 query rows).
// S = Q*K^T via m16n8k8 (K row-major [j][d] = native NT B operand).
// P routed through per-warp smem rows; O += P*V with V staged transposed [d][j].
// Stride 68 => all mma fragment loads bank-conflict-free.
// ---------------------------------------------------------------------------
#define AST 68

__global__ __launch_bounds__(128)
void attn_mma()
{
    extern __shared__ unsigned smu[];
    unsigned* Qs = smu;                 // [q][d]  64 x 68
    unsigned* Ks = smu + 64 * AST;      // [j][d]
    unsigned* Vt = smu + 2 * 64 * AST;  // [d][j]
    unsigned* Ps = smu + 3 * 64 * AST;  // [q][j]

    int tid  = threadIdx.x;
    int lane = tid & 31;
    int wid  = tid >> 5;
    int g = lane >> 2;
    int t = lane & 3;

    int bh = blockIdx.y;
    int i0 = blockIdx.x * 64;

    const float* Qg = g_Q + (size_t)bh * SEQ * HD;
    const float* Kg = g_K + (size_t)bh * SEQ * HD;
    const float* Vg = g_V + (size_t)bh * SEQ * HD;

    // Load Q tile (scaled by 1/sqrt(64), exact in tf32)
    {
        int q = tid >> 1, half = tid & 1;
#pragma unroll
        for (int v = 0; v < 8; v++) {
            int c4 = half * 32 + v * 4;
            float4 qv = *(const float4*)(Qg + (size_t)(i0 + q) * HD + c4);
            uint4 u;
            u.x = f2tf32(qv.x * 0.125f);
            u.y = f2tf32(qv.y * 0.125f);
            u.z = f2tf32(qv.z * 0.125f);
            u.w = f2tf32(qv.w * 0.125f);
            *(uint4*)&Qs[q * AST + c4] = u;
        }
    }

    int rbase = wid * 16;
    int iq0 = i0 + rbase + g;
    int iq1 = iq0 + 8;

    float m0 = -1e30f, m1 = -1e30f, l0 = 0.f, l1 = 0.f;
    float oacc[8][4];
#pragma unroll
    for (int nt = 0; nt < 8; nt++)
#pragma unroll
        for (int i = 0; i < 4; i++) oacc[nt][i] = 0.f;

    int kv_lo = i0 - (WIN - 1);
    if (kv_lo < 0) kv_lo = 0;
    int cs0 = (kv_lo / 64) * 64;

    for (int cs = cs0; cs <= i0; cs += 64) {
        __syncthreads();   // previous iteration's Ks/Vt reads complete
        // Load K chunk [j][d] and V chunk transposed [d][j]
        {
            int j = tid >> 1, half = tid & 1;
#pragma unroll
            for (int v = 0; v < 8; v++) {
                int c4 = half * 32 + v * 4;
                float4 kv = *(const float4*)(Kg + (size_t)(cs + j) * HD + c4);
                uint4 u;
                u.x = f2tf32(kv.x); u.y = f2tf32(kv.y);
                u.z = f2tf32(kv.z); u.w = f2tf32(kv.w);
                *(uint4*)&Ks[j * AST + c4] = u;
                float4 vv = *(const float4*)(Vg + (size_t)(cs + j) * HD + c4);
                Vt[(c4 + 0) * AST + j] = f2tf32(vv.x);
                Vt[(c4 + 1) * AST + j] = f2tf32(vv.y);
                Vt[(c4 + 2) * AST + j] = f2tf32(vv.z);
                Vt[(c4 + 3) * AST + j] = f2tf32(vv.w);
            }
        }
        __syncthreads();

        // S = Q*K^T : warp rows [rbase, rbase+16), all 64 j columns
        float sacc[8][4];
#pragma unroll
        for (int nt = 0; nt < 8; nt++)
#pragma unroll
            for (int i = 0; i < 4; i++) sacc[nt][i] = 0.f;

#pragma unroll
        for (int kk = 0; kk < 8; kk++) {
            int c = kk * 8 + t;
            unsigned af[4];
            af[0] = Qs[(rbase + g) * AST + c];
            af[1] = Qs[(rbase + g + 8) * AST + c];
            af[2] = Qs[(rbase + g) * AST + c + 4];
            af[3] = Qs[(rbase + g + 8) * AST + c + 4];
#pragma unroll
            for (int nt = 0; nt < 8; nt++) {
                unsigned bf[2];
                bf[0] = Ks[(nt * 8 + g) * AST + c];
                bf[1] = Ks[(nt * 8 + g) * AST + c + 4];
                mma_tf32(sacc[nt], af, bf);
            }
        }

        // Mask + online softmax. Thread owns rows iq0 (c0,c1) and iq1 (c2,c3),
        // columns j = cs + nt*8 + 2t + {0,1}.
        float rmax0 = -1e30f, rmax1 = -1e30f;
#pragma unroll
        for (int nt = 0; nt < 8; nt++) {
#pragma unroll
            for (int e = 0; e < 2; e++) {
                int j = cs + nt * 8 + 2 * t + e;
                if (!((j <= iq0) && (j > iq0 - WIN))) sacc[nt][e] = -1e30f;
                if (!((j <= iq1) && (j > iq1 - WIN))) sacc[nt][2 + e] = -1e30f;
                rmax0 = fmaxf(rmax0, sacc[nt][e]);
                rmax1 = fmaxf(rmax1, sacc[nt][2 + e]);
            }
        }
#pragma unroll
        for (int msk = 1; msk < 4; msk <<= 1) {
            rmax0 = fmaxf(rmax0, __shfl_xor_sync(0xffffffffu, rmax0, msk));
            rmax1 = fmaxf(rmax1, __shfl_xor_sync(0xffffffffu, rmax1, msk));
        }

        float mn0 = fmaxf(m0, rmax0);
        float mn1 = fmaxf(m1, rmax1);
        float cor0 = __expf(m0 - mn0);
        float cor1 = __expf(m1 - mn1);
        m0 = mn0; m1 = mn1;

        float rs0 = 0.f, rs1 = 0.f;
#pragma unroll
        for (int nt = 0; nt < 8; nt++) {
            float p0 = __expf(sacc[nt][0] - mn0);
            float p1 = __expf(sacc[nt][1] - mn0);
            float p2 = __expf(sacc[nt][2] - mn1);
            float p3 = __expf(sacc[nt][3] - mn1);
            rs0 += p0 + p1;
            rs1 += p2 + p3;
            // Store P (tf32) to warp-private smem rows
            int col = nt * 8 + 2 * t;
            uint2 u0 = { f2tf32(p0), f2tf32(p1) };
            uint2 u1 = { f2tf32(p2), f2tf32(p3) };
            *(uint2*)&Ps[(rbase + g) * AST + col]     = u0;
            *(uint2*)&Ps[(rbase + g + 8) * AST + col] = u1;
        }
#pragma unroll
        for (int msk = 1; msk < 4; msk <<= 1) {
            rs0 += __shfl_xor_sync(0xffffffffu, rs0, msk);
            rs1 += __shfl_xor_sync(0xffffffffu, rs1, msk);
        }
        l0 = l0 * cor0 + rs0;
        l1 = l1 * cor1 + rs1;
#pragma unroll
        for (int nt = 0; nt < 8; nt++) {
            oacc[nt][0] *= cor0; oacc[nt][1] *= cor0;
            oacc[nt][2] *= cor1; oacc[nt][3] *= cor1;
        }
        __syncwarp();

        // O += P * V  (A = Ps rows, B = Vt[d][j] as col-major [n=d][k=j])
#pragma unroll
        for (int kk = 0; kk < 8; kk++) {
            int c = kk * 8 + t;
            unsigned af[4];
            af[0] = Ps[(rbase + g) * AST + c];
            af[1] = Ps[(rbase + g + 8) * AST + c];
            af[2] = Ps[(rbase + g) * AST + c + 4];
            af[3] = Ps[(rbase + g + 8) * AST + c + 4];
#pragma unroll
            for (int nt = 0; nt < 8; nt++) {
                unsigned bf[2];
                bf[0] = Vt[(nt * 8 + g) * AST + c];
                bf[1] = Vt[(nt * 8 + g) * AST + c + 4];
                mma_tf32(oacc[nt], af, bf);
            }
        }
    }

    // Normalize + write: g_O[(b*SEQ+iq)*1024 + h*64 + d]
    float inv0 = 1.f / l0;
    float inv1 = 1.f / l1;
    int b = bh / NHEADS;
    int h = bh % NHEADS;
    float* O0 = g_O + (size_t)(b * SEQ + iq0) * D_MODEL + h * HD;
    float* O1 = g_O + (size_t)(b * SEQ + iq1) * D_MODEL + h * HD;
#pragma unroll
    for (int nt = 0; nt < 8; nt++) {
        int d = nt * 8 + 2 * t;
        float2 v0 = { oacc[nt][0] * inv0, oacc[nt][1] * inv0 };
        float2 v1 = { oacc[nt][2] * inv1, oacc[nt][3] * inv1 };
        *(float2*)(O0 + d) = v0;
        *(float2*)(O1 + d) = v1;
    }
}

// ---------------------------------------------------------------------------
extern "C" void kernel_launch(void* const* d_in, const int* in_sizes, int n_in,
                              void* d_out, int out_size)
{
    const float* x  = (const float*)d_in[0];   // [2,2048,1024]
    const float* w1 = (const float*)d_in[1];   // [3072,1024]
    const float* b1 = (const float*)d_in[2];   // [3072]
    const float* w2 = (const float*)d_in[3];   // [1024,1024]
    const float* b2 = (const float*)d_in[4];   // [1024]
    float* out = (float*)d_out;                // [2,2048,1024]

    const int M = BATCH * SEQ;                 // 4096

    // 1) QKV projection (tf32 tensor cores), routed into g_Q/g_K/g_V
    {
        dim3 grid(3 * D_MODEL / 128, M / 128); // 24 x 32
        gemm_tf32<0><<<grid, 256>>>(x, w1, b1, nullptr, M, 3 * D_MODEL, D_MODEL);
    }

    // 2) Sliding-window attention (tf32 tensor cores)
    {
        int smem = 4 * 64 * AST * sizeof(unsigned);  // 69632 B
        cudaFuncSetAttribute(attn_mma,
                             cudaFuncAttributeMaxDynamicSharedMemorySize, smem);
        dim3 grid(SEQ / 64, BATCH * NHEADS);   // 32 x 32
        attn_mma<<<grid, 128, smem>>>();
    }

    // 3) Output projection (tf32 tensor cores)
    {
        dim3 grid(D_MODEL / 128, M / 128);     // 8 x 32
        gemm_tf32<1><<<grid, 256>>>(nullptr, w2, b2, out, M, D_MODEL, D_MODEL);
    }
}